// round 10
// baseline (speedup 1.0000x reference)
#include <cuda_runtime.h>
#include <cuda_fp16.h>
#include <cstdint>

// Problem constants
#define TQ 4096   // tokens
#define HD 1024   // hidden
#define FD 2048   // ffn dim (w1 rows: [gate(0..FD), up(FD..2FD)])
#define NE 8      // experts
#define NK 2      // top-k

// ---------------------------------------------------------------------------
// Scratch (device globals; runtime allocation is forbidden)
// ---------------------------------------------------------------------------
__device__ int    g_counts[NE];
__device__ int    g_tok[NE * TQ];
__device__ float  g_wt[TQ * NK];
__device__ float  g_y[(size_t)TQ * NK * HD];
__device__ __half g_acth[(size_t)TQ * NK * FD];      // fp16 silu(g)*u
__device__ __half g_hsh[(size_t)TQ * HD];            // fp16 hs
__device__ __half g_w1h[(size_t)NE * 2 * FD * HD];   // fp16 w1 (67MB)
__device__ __half g_w2h[(size_t)NE * HD * FD];       // fp16 w2 (34MB)

// ---------------------------------------------------------------------------
// Helpers
// ---------------------------------------------------------------------------
__device__ __forceinline__ uint32_t f2h2(float lo, float hi) {
    uint32_t r;   // f16x2: lo half <- 2nd operand
    asm("cvt.rn.f16x2.f32 %0, %1, %2;" : "=r"(r) : "f"(hi), "f"(lo));
    return r;
}
__device__ __forceinline__ uint32_t s2u(const void* p) {
    uint32_t a;
    asm("{ .reg .u64 t; cvta.to.shared.u64 t, %1; cvt.u32.u64 %0, t; }"
        : "=r"(a) : "l"(p));
    return a;
}
// fp16 m16n8k16, fp32 accumulate: 2048 MACs per instruction.
__device__ __forceinline__ void mma_f16(float* c, const uint32_t* a,
                                        uint32_t b0, uint32_t b1) {
    asm volatile(
        "mma.sync.aligned.m16n8k16.row.col.f32.f16.f16.f32 "
        "{%0,%1,%2,%3}, {%4,%5,%6,%7}, {%8,%9}, {%0,%1,%2,%3};"
        : "+f"(c[0]), "+f"(c[1]), "+f"(c[2]), "+f"(c[3])
        : "r"(a[0]), "r"(a[1]), "r"(a[2]), "r"(a[3]), "r"(b0), "r"(b1));
}
// ldmatrix x4 b16: 4x (8 rows x 16B). Delivers the canonical fp16 fragments.
__device__ __forceinline__ void ldsm4(uint32_t* r, uint32_t addr) {
    asm volatile("ldmatrix.sync.aligned.m8n8.x4.shared.b16 {%0,%1,%2,%3}, [%4];"
                 : "=r"(r[0]), "=r"(r[1]), "=r"(r[2]), "=r"(r[3]) : "r"(addr));
}
__device__ __forceinline__ float silu(float x) {
    return x / (1.0f + __expf(-x));
}

// 16B cp.async with zero-fill when sz==0 (invalid A rows)
#define CPA16(sa, ga, sz)                                                      \
    asm volatile("cp.async.cg.shared.global [%0], [%1], 16, %2;"               \
                 :: "r"(sa), "l"(ga), "r"(sz) : "memory")

// Stage: A 64 rows x 64 halves (8KB) + B 128 rows x 64 halves (16KB) = 24KB.
// Row = 128B = 8 x 16B chunks; swizzle: phys chunk = chunk ^ (row & 7).
#define STAGE_BYTES 24576u

// 128 threads: A rows 64 (2 thr/row, 4 chunks each), B rows 128 (1 thr, 8 ch).
#define LOAD_STAGE(KC, ST) do {                                                \
    uint32_t _b = sbase + (uint32_t)(ST) * STAGE_BYTES;                        \
    const __half* _a = aptr + (KC);                                            \
    const __half* _w = bptr + (KC);                                            \
    _Pragma("unroll")                                                          \
    for (int _c = 0; _c < 4; _c++)                                             \
        CPA16(_b + offA[_c], _a + _c * 8, za);                                 \
    _Pragma("unroll")                                                          \
    for (int _c = 0; _c < 8; _c++)                                             \
        CPA16(_b + 8192u + offB[_c], _w + _c * 8, 16u);                        \
    asm volatile("cp.async.commit_group;" ::: "memory");                       \
} while (0)

// Fragment load for one k16 step KS into register buffer BUF.
#define LDFRAG(KS, BUF) do {                                                   \
    _Pragma("unroll")                                                          \
    for (int nip = 0; nip < 4; nip++)                                          \
        ldsm4(br[BUF][nip], _sB + aoffB + nip * 2048u + xb[KS]);               \
    _Pragma("unroll")                                                          \
    for (int mi = 0; mi < 2; mi++)                                             \
        ldsm4(ar[BUF][mi], _sA + aoffA + mi * 2048u + xa[KS]);                 \
} while (0)

// MMAs for one k16 step from buffer BUF (2 mi x 8 ni).
#define MMAFRAG(BUF)                                                           \
    _Pragma("unroll")                                                          \
    for (int mi = 0; mi < 2; mi++)                                             \
        _Pragma("unroll")                                                      \
        for (int ni = 0; ni < 8; ni++)                                         \
            mma_f16(acc[mi][ni], ar[BUF][mi],                                  \
                    br[BUF][ni >> 1][2 * (ni & 1)],                            \
                    br[BUF][ni >> 1][2 * (ni & 1) + 1])

// Double-buffered fragment pipeline for one K=64 chunk: LDSM of step k+1
// overlaps the MMAs of step k (crossbar and tensor pipe run concurrently).
#define CHUNK_MMA(IST) do {                                                    \
    uint32_t _sA = sbase + (uint32_t)(IST) * STAGE_BYTES;                      \
    uint32_t _sB = _sA + 8192u;                                                \
    uint32_t br[2][4][4], ar[2][2][4];                                         \
    LDFRAG(0, 0);                                                              \
    LDFRAG(1, 1);                                                              \
    MMAFRAG(0);                                                                \
    LDFRAG(2, 0);                                                              \
    MMAFRAG(1);                                                                \
    LDFRAG(3, 1);                                                              \
    MMAFRAG(0);                                                                \
    MMAFRAG(1);                                                                \
} while (0)

// ---------------------------------------------------------------------------
// Kernel 0b: fp32 -> fp16 round a tensor into scratch (8 floats/thread)
// ---------------------------------------------------------------------------
__global__ __launch_bounds__(256) void k_cvt_h(const float4* __restrict__ src,
                                               uint4* __restrict__ dst, int n8) {
    int i = blockIdx.x * 256 + threadIdx.x;
    if (i >= n8) return;
    float4 v0 = src[2 * i], v1 = src[2 * i + 1];
    uint4 o;
    o.x = f2h2(v0.x, v0.y);
    o.y = f2h2(v0.z, v0.w);
    o.z = f2h2(v1.x, v1.y);
    o.w = f2h2(v1.z, v1.w);
    dst[i] = o;
}

// ---------------------------------------------------------------------------
// Kernel 1: router. One warp per token.
// ---------------------------------------------------------------------------
__global__ __launch_bounds__(256) void k_router(const float* __restrict__ hs,
                                                const float* __restrict__ gw,
                                                float* __restrict__ logits_out) {
    __shared__ float sg[NE * HD];
    int tid = threadIdx.x;
    for (int i = tid; i < NE * HD; i += 256) sg[i] = gw[i];
    __syncthreads();

    int warp = tid >> 5, lane = tid & 31;
    int t = blockIdx.x * 8 + warp;
    const float* x = hs + (size_t)t * HD;

    float acc[NE];
#pragma unroll
    for (int e = 0; e < NE; e++) acc[e] = 0.f;
    for (int j = lane; j < HD; j += 32) {
        float xv = x[j];
#pragma unroll
        for (int e = 0; e < NE; e++) acc[e] += xv * sg[e * HD + j];
    }
#pragma unroll
    for (int e = 0; e < NE; e++) {
#pragma unroll
        for (int off = 16; off; off >>= 1)
            acc[e] += __shfl_xor_sync(0xffffffffu, acc[e], off);
    }

    if (lane == 0) {
        if (logits_out) {
#pragma unroll
            for (int e = 0; e < NE; e++) logits_out[(size_t)t * NE + e] = acc[e];
        }
        float m1 = acc[0]; int i0 = 0;
#pragma unroll
        for (int e = 1; e < NE; e++) if (acc[e] > m1) { m1 = acc[e]; i0 = e; }
        float m2 = -3.4e38f; int i1 = 0;
#pragma unroll
        for (int e = 0; e < NE; e++)
            if (e != i0 && acc[e] > m2) { m2 = acc[e]; i1 = e; }
        float e2v = __expf(m2 - m1);
        float inv = 1.0f / (1.0f + e2v);

        int p0 = atomicAdd(&g_counts[i0], 1);
        g_tok[i0 * TQ + p0] = t * 2;
        g_wt[t * 2] = inv;
        int p1 = atomicAdd(&g_counts[i1], 1);
        g_tok[i1 * TQ + p1] = t * 2 + 1;
        g_wt[t * 2 + 1] = e2v * inv;
    }
}

// ---------------------------------------------------------------------------
// Kernel 2: FFN1 grouped GEMM with fused SiLU*up, fp16 MMA.
// CTA tile 64 rows x 128 mma cols (64 gate cols interleaved with 64 up).
// 4 warps in a 2x2 grid, warp tile 32x64. 3-stage cp.async ring, 3 CTAs/SM.
// grid = (FD/64 = 32, NE*64), 128 threads.
// ---------------------------------------------------------------------------
__global__ __launch_bounds__(128, 3) void k_ffn1() {
    int e  = blockIdx.y >> 6;
    int mt = blockIdx.y & 63;
    int cnt = g_counts[e];
    int m0 = mt * 64;
    if (m0 >= cnt) return;
    int n0 = blockIdx.x * 64;

    extern __shared__ char dsm[];
    __shared__ int s_tok[64];

    int tid = threadIdx.x;
    if (tid < 64) {
        int idx = m0 + tid;
        s_tok[tid] = (idx < cnt) ? g_tok[e * TQ + idx] : -1;
    }
    __syncthreads();

    int warp = tid >> 5, lane = tid & 31;
    int wm = warp >> 1, wn = warp & 1;      // 2x2 warps, warp tile 32x64
    int g = lane >> 2, tg = lane & 3;

    // A loader: 2 threads per row (64 rows), 4 x 16B chunks each
    int rowA = tid >> 1, cbA = (tid & 1) * 4;
    int atok = s_tok[rowA];
    uint32_t za = (atok >= 0) ? 16u : 0u;
    const __half* aptr = g_hsh + (size_t)(atok >= 0 ? (atok >> 1) : 0) * HD + cbA * 8;
    // B loader: 1 thread per row (128 rows, interleaved gate/up), 8 x 16B
    int rowB = tid;
    int wrow = (rowB & 1) ? (FD + n0 + (rowB >> 1)) : (n0 + (rowB >> 1));
    const __half* bptr = g_w1h + ((size_t)e * 2 * FD + wrow) * HD;

    uint32_t sbase = s2u(dsm);
    uint32_t offA[4], offB[8];
#pragma unroll
    for (int c = 0; c < 4; c++)
        offA[c] = (uint32_t)(rowA * 128 + (((cbA + c) ^ (rowA & 7)) << 4));
#pragma unroll
    for (int c = 0; c < 8; c++)
        offB[c] = (uint32_t)(rowB * 128 + ((c ^ (rowB & 7)) << 4));

    // ldmatrix per-lane address components (row = 128B)
    int j = lane >> 3, r = lane & 7;
    uint32_t aoffA = (uint32_t)((wm * 32 + ((j & 1) << 3) + r) * 128);
    uint32_t aoffB = (uint32_t)((wn * 64 + ((j >> 1) << 3) + r) * 128);
    int cjA = j >> 1, cjB = j & 1;
    uint32_t xa[4], xb[4];
#pragma unroll
    for (int ks = 0; ks < 4; ks++) {
        xa[ks] = (uint32_t)((((2 * ks + cjA) ^ r) << 4));
        xb[ks] = (uint32_t)((((2 * ks + cjB) ^ r) << 4));
    }

    float acc[2][8][4];
#pragma unroll
    for (int mi = 0; mi < 2; mi++)
#pragma unroll
        for (int ni = 0; ni < 8; ni++)
#pragma unroll
            for (int q = 0; q < 4; q++) acc[mi][ni][q] = 0.f;

    const int NKC = HD / 64;   // 16
    LOAD_STAGE(0, 0);
    LOAD_STAGE(64, 1);

    for (int i = 0; i < NKC; i++) {
        asm volatile("cp.async.wait_group 1;" ::: "memory");
        __syncthreads();
        if (i + 2 < NKC) {
            int st = (i + 2) % 3;
            LOAD_STAGE((i + 2) * 64, st);
        } else {
            asm volatile("cp.async.commit_group;" ::: "memory");
        }
        CHUNK_MMA(i % 3);
    }

    // Epilogue: even mma col = gate, odd = up; write fp16 activation.
#pragma unroll
    for (int mi = 0; mi < 2; mi++) {
        int rl0 = wm * 32 + mi * 16 + g;
        int t0 = s_tok[rl0], t1 = s_tok[rl0 + 8];
#pragma unroll
        for (int ni = 0; ni < 8; ni++) {
            int colg = n0 + wn * 32 + ni * 4 + tg;
            float* c = acc[mi][ni];
            if (t0 >= 0)
                g_acth[(size_t)t0 * FD + colg] = __float2half_rn(silu(c[0]) * c[1]);
            if (t1 >= 0)
                g_acth[(size_t)t1 * FD + colg] = __float2half_rn(silu(c[2]) * c[3]);
        }
    }
}

// ---------------------------------------------------------------------------
// Kernel 3: FFN2 grouped GEMM (act @ w2[e]^T), scaled by combine weight.
// CTA tile 64 x 128, warp tile 32x64. grid = (HD/128 = 8, NE*64), 128 thr.
// ---------------------------------------------------------------------------
__global__ __launch_bounds__(128, 3) void k_ffn2() {
    int e  = blockIdx.y >> 6;
    int mt = blockIdx.y & 63;
    int cnt = g_counts[e];
    int m0 = mt * 64;
    if (m0 >= cnt) return;
    int n0 = blockIdx.x * 128;

    extern __shared__ char dsm[];
    __shared__ int s_tok[64];

    int tid = threadIdx.x;
    if (tid < 64) {
        int idx = m0 + tid;
        s_tok[tid] = (idx < cnt) ? g_tok[e * TQ + idx] : -1;
    }
    __syncthreads();

    int warp = tid >> 5, lane = tid & 31;
    int wm = warp >> 1, wn = warp & 1;      // 2x2 warps, warp tile 32x64
    int g = lane >> 2, tg = lane & 3;

    int rowA = tid >> 1, cbA = (tid & 1) * 4;
    int atok = s_tok[rowA];
    uint32_t za = (atok >= 0) ? 16u : 0u;
    const __half* aptr = g_acth + (size_t)(atok >= 0 ? atok : 0) * FD + cbA * 8;
    int rowB = tid;
    const __half* bptr = g_w2h + ((size_t)e * HD + n0 + rowB) * FD;

    uint32_t sbase = s2u(dsm);
    uint32_t offA[4], offB[8];
#pragma unroll
    for (int c = 0; c < 4; c++)
        offA[c] = (uint32_t)(rowA * 128 + (((cbA + c) ^ (rowA & 7)) << 4));
#pragma unroll
    for (int c = 0; c < 8; c++)
        offB[c] = (uint32_t)(rowB * 128 + ((c ^ (rowB & 7)) << 4));

    int j = lane >> 3, r = lane & 7;
    uint32_t aoffA = (uint32_t)((wm * 32 + ((j & 1) << 3) + r) * 128);
    uint32_t aoffB = (uint32_t)((wn * 64 + ((j >> 1) << 3) + r) * 128);
    int cjA = j >> 1, cjB = j & 1;
    uint32_t xa[4], xb[4];
#pragma unroll
    for (int ks = 0; ks < 4; ks++) {
        xa[ks] = (uint32_t)((((2 * ks + cjA) ^ r) << 4));
        xb[ks] = (uint32_t)((((2 * ks + cjB) ^ r) << 4));
    }

    float acc[2][8][4];
#pragma unroll
    for (int mi = 0; mi < 2; mi++)
#pragma unroll
        for (int ni = 0; ni < 8; ni++)
#pragma unroll
            for (int q = 0; q < 4; q++) acc[mi][ni][q] = 0.f;

    const int NKC = FD / 64;   // 32
    LOAD_STAGE(0, 0);
    LOAD_STAGE(64, 1);

    for (int i = 0; i < NKC; i++) {
        asm volatile("cp.async.wait_group 1;" ::: "memory");
        __syncthreads();
        if (i + 2 < NKC) {
            int st = (i + 2) % 3;
            LOAD_STAGE((i + 2) * 64, st);
        } else {
            asm volatile("cp.async.commit_group;" ::: "memory");
        }
        CHUNK_MMA(i % 3);
    }

#pragma unroll
    for (int mi = 0; mi < 2; mi++) {
        int rl0 = wm * 32 + mi * 16 + g;
        int t0 = s_tok[rl0], t1 = s_tok[rl0 + 8];
        float w0 = (t0 >= 0) ? g_wt[t0] : 0.f;
        float w1v = (t1 >= 0) ? g_wt[t1] : 0.f;
#pragma unroll
        for (int ni = 0; ni < 8; ni++) {
            int col = n0 + wn * 64 + ni * 8 + tg * 2;
            float* c = acc[mi][ni];
            if (t0 >= 0)
                *(float2*)(g_y + (size_t)t0 * HD + col) =
                    make_float2(w0 * c[0], w0 * c[1]);
            if (t1 >= 0)
                *(float2*)(g_y + (size_t)t1 * HD + col) =
                    make_float2(w1v * c[2], w1v * c[3]);
        }
    }
}

// ---------------------------------------------------------------------------
// Kernel 4: combine the two expert contributions per token (full overwrite).
// ---------------------------------------------------------------------------
__global__ __launch_bounds__(256) void k_combine(float* __restrict__ out) {
    int i = blockIdx.x * 256 + threadIdx.x;
    int t = i >> 8;
    int c = i & 255;
    float4 a = ((const float4*)(g_y + (size_t)(2 * t) * HD))[c];
    float4 b = ((const float4*)(g_y + (size_t)(2 * t + 1) * HD))[c];
    ((float4*)out)[i] = make_float4(a.x + b.x, a.y + b.y, a.z + b.z, a.w + b.w);
}

// ---------------------------------------------------------------------------
// Launch. ncu captures kernel index 3 = k_ffn1
// (router=0, cvt_w1=1, cvt_hs=2, ffn1=3).
// ---------------------------------------------------------------------------
extern "C" void kernel_launch(void* const* d_in, const int* in_sizes, int n_in,
                              void* d_out, int out_size) {
    const float* hs = (const float*)d_in[0];
    const float* gw = (const float*)d_in[1];
    const float* w1 = (const float*)d_in[2];
    const float* w2 = (const float*)d_in[3];
    float* out = (float*)d_out;
    float* logits = (out_size >= TQ * HD + TQ * NE) ? out + (size_t)TQ * HD
                                                    : nullptr;

    static const int DSMEM = 3 * (int)STAGE_BYTES;   // 72 KB -> 3 CTAs/SM
    static bool attr_done = false;
    if (!attr_done) {
        cudaFuncSetAttribute(k_ffn1, cudaFuncAttributeMaxDynamicSharedMemorySize, DSMEM);
        cudaFuncSetAttribute(k_ffn2, cudaFuncAttributeMaxDynamicSharedMemorySize, DSMEM);
        attr_done = true;
    }

    void* w1h; cudaGetSymbolAddress(&w1h, g_w1h);
    void* w2h; cudaGetSymbolAddress(&w2h, g_w2h);
    void* hsh; cudaGetSymbolAddress(&hsh, g_hsh);
    int*  cnts; cudaGetSymbolAddress((void**)&cnts, g_counts);

    cudaMemsetAsync(cnts, 0, NE * sizeof(int));                       // node, not kernel
    k_router<<<TQ / 8, 256>>>(hs, gw, logits);                        // kernel 0
    k_cvt_h<<<(NE * 2 * FD * HD / 8) / 256, 256>>>((const float4*)w1, // kernel 1
                                                   (uint4*)w1h, NE * 2 * FD * HD / 8);
    k_cvt_h<<<(TQ * HD / 8) / 256, 256>>>((const float4*)hs,          // kernel 2
                                          (uint4*)hsh, TQ * HD / 8);
    k_ffn1<<<dim3(FD / 64, NE * 64), 128, DSMEM>>>();                 // kernel 3 (profiled)
    k_cvt_h<<<(NE * HD * FD / 8) / 256, 256>>>((const float4*)w2,     // kernel 4
                                               (uint4*)w2h, NE * HD * FD / 8);
    k_ffn2<<<dim3(HD / 128, NE * 64), 128, DSMEM>>>();                // kernel 5
    k_combine<<<(TQ * HD / 4) / 256, 256>>>(out);                     // kernel 6
}

// round 11
// speedup vs baseline: 1.4098x; 1.4098x over previous
#include <cuda_runtime.h>
#include <cuda_fp16.h>
#include <cstdint>

// Problem constants
#define TQ 4096   // tokens
#define HD 1024   // hidden
#define FD 2048   // ffn dim (w1 rows: [gate(0..FD), up(FD..2FD)])
#define NE 8      // experts
#define NK 2      // top-k

// ---------------------------------------------------------------------------
// Scratch (device globals; runtime allocation is forbidden)
// ---------------------------------------------------------------------------
__device__ int    g_counts[NE];
__device__ int    g_tok[NE * TQ];
__device__ float  g_wt[TQ * NK];
__device__ float  g_y[(size_t)TQ * NK * HD];
__device__ __half g_acth[(size_t)TQ * NK * FD];      // fp16 silu(g)*u
__device__ __half g_hsh[(size_t)TQ * HD];            // fp16 hs (written by router)
__device__ __half g_w1h[(size_t)NE * 2 * FD * HD];   // fp16 w1 (67MB)
__device__ __half g_w2h[(size_t)NE * HD * FD];       // fp16 w2 (34MB)

// ---------------------------------------------------------------------------
// Helpers
// ---------------------------------------------------------------------------
__device__ __forceinline__ uint32_t f2h2(float lo, float hi) {
    uint32_t r;   // f16x2: lo half <- 2nd operand
    asm("cvt.rn.f16x2.f32 %0, %1, %2;" : "=r"(r) : "f"(hi), "f"(lo));
    return r;
}
__device__ __forceinline__ uint32_t s2u(const void* p) {
    uint32_t a;
    asm("{ .reg .u64 t; cvta.to.shared.u64 t, %1; cvt.u32.u64 %0, t; }"
        : "=r"(a) : "l"(p));
    return a;
}
// fp16 m16n8k16, fp32 accumulate: 2048 MACs per instruction.
__device__ __forceinline__ void mma_f16(float* c, const uint32_t* a,
                                        uint32_t b0, uint32_t b1) {
    asm volatile(
        "mma.sync.aligned.m16n8k16.row.col.f32.f16.f16.f32 "
        "{%0,%1,%2,%3}, {%4,%5,%6,%7}, {%8,%9}, {%0,%1,%2,%3};"
        : "+f"(c[0]), "+f"(c[1]), "+f"(c[2]), "+f"(c[3])
        : "r"(a[0]), "r"(a[1]), "r"(a[2]), "r"(a[3]), "r"(b0), "r"(b1));
}
// ldmatrix x4 b16: 4x (8 rows x 16B). Delivers the canonical fp16 fragments.
__device__ __forceinline__ void ldsm4(uint32_t* r, uint32_t addr) {
    asm volatile("ldmatrix.sync.aligned.m8n8.x4.shared.b16 {%0,%1,%2,%3}, [%4];"
                 : "=r"(r[0]), "=r"(r[1]), "=r"(r[2]), "=r"(r[3]) : "r"(addr));
}
__device__ __forceinline__ float silu(float x) {
    return x / (1.0f + __expf(-x));
}

// 16B cp.async with zero-fill when sz==0 (invalid A rows)
#define CPA16(sa, ga, sz)                                                      \
    asm volatile("cp.async.cg.shared.global [%0], [%1], 16, %2;"               \
                 :: "r"(sa), "l"(ga), "r"(sz) : "memory")

// Stage: A 128 rows x 64 halves (16KB) + B 128 rows x 64 halves (16KB) = 32KB.
// Row = 128B = 8 x 16B chunks; swizzle: phys chunk = chunk ^ (row & 7).
// 256 threads: 2 threads per row, 4 chunks each for A and B.
#define LOAD_STAGE(KC, ST) do {                                                \
    uint32_t _b = sbase + (uint32_t)(ST) * 32768u;                             \
    const __half* _a = aptr + (KC);                                            \
    const __half* _w = bptr + (KC);                                            \
    _Pragma("unroll")                                                          \
    for (int _c = 0; _c < 4; _c++) {                                           \
        CPA16(_b + offs[_c], _a + _c * 8, za);                                 \
        CPA16(_b + 16384u + offs[_c], _w + _c * 8, 16u);                       \
    }                                                                          \
    asm volatile("cp.async.commit_group;" ::: "memory");                       \
} while (0)

// Fragment load for one k16 step KS into register buffer BUF.
#define LDFRAG(KS, BUF) do {                                                   \
    _Pragma("unroll")                                                          \
    for (int nip = 0; nip < 4; nip++)                                          \
        ldsm4(br[BUF][nip], _sB + aoffB + nip * 2048u + xb[KS]);               \
    _Pragma("unroll")                                                          \
    for (int mi = 0; mi < 2; mi++)                                             \
        ldsm4(ar[BUF][mi], _sA + aoffA + mi * 2048u + xa[KS]);                 \
} while (0)

// MMAs for one k16 step from buffer BUF (2 mi x 8 ni).
#define MMAFRAG(BUF)                                                           \
    _Pragma("unroll")                                                          \
    for (int mi = 0; mi < 2; mi++)                                             \
        _Pragma("unroll")                                                      \
        for (int ni = 0; ni < 8; ni++)                                         \
            mma_f16(acc[mi][ni], ar[BUF][mi],                                  \
                    br[BUF][ni >> 1][2 * (ni & 1)],                            \
                    br[BUF][ni >> 1][2 * (ni & 1) + 1])

// Double-buffered fragment pipeline for one K=64 chunk: LDSM of step k+1
// issue before the MMAs of step k, so crossbar and tensor pipe overlap
// instead of alternating.
#define CHUNK_MMA(IST) do {                                                    \
    uint32_t _sA = sbase + (uint32_t)(IST) * 32768u;                           \
    uint32_t _sB = _sA + 16384u;                                               \
    uint32_t br[2][4][4], ar[2][2][4];                                         \
    LDFRAG(0, 0);                                                              \
    LDFRAG(1, 1);                                                              \
    MMAFRAG(0);                                                                \
    LDFRAG(2, 0);                                                              \
    MMAFRAG(1);                                                                \
    LDFRAG(3, 1);                                                              \
    MMAFRAG(0);                                                                \
    MMAFRAG(1);                                                                \
} while (0)

// ---------------------------------------------------------------------------
// Kernel 0b: fp32 -> fp16 round a tensor into scratch (8 floats/thread)
// ---------------------------------------------------------------------------
__global__ __launch_bounds__(256) void k_cvt_h(const float4* __restrict__ src,
                                               uint4* __restrict__ dst, int n8) {
    int i = blockIdx.x * 256 + threadIdx.x;
    if (i >= n8) return;
    float4 v0 = src[2 * i], v1 = src[2 * i + 1];
    uint4 o;
    o.x = f2h2(v0.x, v0.y);
    o.y = f2h2(v0.z, v0.w);
    o.z = f2h2(v1.x, v1.y);
    o.w = f2h2(v1.z, v1.w);
    dst[i] = o;
}

// ---------------------------------------------------------------------------
// Kernel 1: router. One warp per token. Also emits fp16 hs (fused cvt).
// ---------------------------------------------------------------------------
__global__ __launch_bounds__(256) void k_router(const float* __restrict__ hs,
                                                const float* __restrict__ gw,
                                                float* __restrict__ logits_out,
                                                __half* __restrict__ hsh_out) {
    __shared__ float sg[NE * HD];
    int tid = threadIdx.x;
    for (int i = tid; i < NE * HD; i += 256) sg[i] = gw[i];
    __syncthreads();

    int warp = tid >> 5, lane = tid & 31;
    int t = blockIdx.x * 8 + warp;
    const float* x = hs + (size_t)t * HD;
    __half* xo = hsh_out + (size_t)t * HD;

    float acc[NE];
#pragma unroll
    for (int e = 0; e < NE; e++) acc[e] = 0.f;
    for (int j = lane; j < HD; j += 32) {
        float xv = x[j];
        xo[j] = __float2half_rn(xv);
#pragma unroll
        for (int e = 0; e < NE; e++) acc[e] += xv * sg[e * HD + j];
    }
#pragma unroll
    for (int e = 0; e < NE; e++) {
#pragma unroll
        for (int off = 16; off; off >>= 1)
            acc[e] += __shfl_xor_sync(0xffffffffu, acc[e], off);
    }

    if (lane == 0) {
        if (logits_out) {
#pragma unroll
            for (int e = 0; e < NE; e++) logits_out[(size_t)t * NE + e] = acc[e];
        }
        float m1 = acc[0]; int i0 = 0;
#pragma unroll
        for (int e = 1; e < NE; e++) if (acc[e] > m1) { m1 = acc[e]; i0 = e; }
        float m2 = -3.4e38f; int i1 = 0;
#pragma unroll
        for (int e = 0; e < NE; e++)
            if (e != i0 && acc[e] > m2) { m2 = acc[e]; i1 = e; }
        float e2v = __expf(m2 - m1);
        float inv = 1.0f / (1.0f + e2v);

        int p0 = atomicAdd(&g_counts[i0], 1);
        g_tok[i0 * TQ + p0] = t * 2;
        g_wt[t * 2] = inv;
        int p1 = atomicAdd(&g_counts[i1], 1);
        g_tok[i1 * TQ + p1] = t * 2 + 1;
        g_wt[t * 2 + 1] = e2v * inv;
    }
}

// ---------------------------------------------------------------------------
// Kernel 2: FFN1 grouped GEMM with fused SiLU*up, fp16 MMA.
// CTA tile 128 rows x 128 mma cols (64 gate cols interleaved with 64 up).
// 4x2 warps, warp tile 32x64. 3-stage cp.async ring (K=64/stage), 2 CTAs/SM.
// grid = (FD/64 = 32, NE*32), 256 threads.
// ---------------------------------------------------------------------------
__global__ __launch_bounds__(256, 2) void k_ffn1() {
    int e  = blockIdx.y >> 5;
    int mt = blockIdx.y & 31;
    int cnt = g_counts[e];
    int m0 = mt * 128;
    if (m0 >= cnt) return;
    int n0 = blockIdx.x * 64;

    extern __shared__ char dsm[];
    __shared__ int s_tok[128];

    int tid = threadIdx.x;
    if (tid < 128) {
        int idx = m0 + tid;
        s_tok[tid] = (idx < cnt) ? g_tok[e * TQ + idx] : -1;
    }
    __syncthreads();

    int warp = tid >> 5, lane = tid & 31;
    int wm = warp >> 1, wn = warp & 1;      // 4x2 warps, warp tile 32x64
    int g = lane >> 2, tg = lane & 3;

    // loader: 2 threads per tile row, 4 x 16B (8 halves) chunks each
    int lrow = tid >> 1, lcb = (tid & 1) * 4;
    int atok = s_tok[lrow];
    uint32_t za = (atok >= 0) ? 16u : 0u;
    const __half* aptr = g_hsh + (size_t)(atok >= 0 ? (atok >> 1) : 0) * HD + lcb * 8;
    int wrow = (lrow & 1) ? (FD + n0 + (lrow >> 1)) : (n0 + (lrow >> 1));
    const __half* bptr = g_w1h + ((size_t)e * 2 * FD + wrow) * HD + lcb * 8;

    uint32_t sbase = s2u(dsm);
    uint32_t offs[4];
#pragma unroll
    for (int c = 0; c < 4; c++)
        offs[c] = (uint32_t)(lrow * 128 + (((lcb + c) ^ (lrow & 7)) << 4));

    // ldmatrix per-lane address components (row = 128B)
    int j = lane >> 3, r = lane & 7;
    uint32_t aoffA = (uint32_t)((wm * 32 + ((j & 1) << 3) + r) * 128);
    uint32_t aoffB = (uint32_t)((wn * 64 + ((j >> 1) << 3) + r) * 128);
    int cjA = j >> 1, cjB = j & 1;
    uint32_t xa[4], xb[4];
#pragma unroll
    for (int ks = 0; ks < 4; ks++) {
        xa[ks] = (uint32_t)((((2 * ks + cjA) ^ r) << 4));
        xb[ks] = (uint32_t)((((2 * ks + cjB) ^ r) << 4));
    }

    float acc[2][8][4];
#pragma unroll
    for (int mi = 0; mi < 2; mi++)
#pragma unroll
        for (int ni = 0; ni < 8; ni++)
#pragma unroll
            for (int q = 0; q < 4; q++) acc[mi][ni][q] = 0.f;

    const int NKC = HD / 64;   // 16
    LOAD_STAGE(0, 0);
    LOAD_STAGE(64, 1);

    for (int i = 0; i < NKC; i++) {
        asm volatile("cp.async.wait_group 1;" ::: "memory");
        __syncthreads();
        if (i + 2 < NKC) {
            int st = (i + 2) % 3;
            LOAD_STAGE((i + 2) * 64, st);
        } else {
            asm volatile("cp.async.commit_group;" ::: "memory");
        }
        CHUNK_MMA(i % 3);
    }

    // Epilogue: even mma col = gate, odd = up; write fp16 activation.
#pragma unroll
    for (int mi = 0; mi < 2; mi++) {
        int rl0 = wm * 32 + mi * 16 + g;
        int t0 = s_tok[rl0], t1 = s_tok[rl0 + 8];
#pragma unroll
        for (int ni = 0; ni < 8; ni++) {
            int colg = n0 + wn * 32 + ni * 4 + tg;
            float* c = acc[mi][ni];
            if (t0 >= 0)
                g_acth[(size_t)t0 * FD + colg] = __float2half_rn(silu(c[0]) * c[1]);
            if (t1 >= 0)
                g_acth[(size_t)t1 * FD + colg] = __float2half_rn(silu(c[2]) * c[3]);
        }
    }
}

// ---------------------------------------------------------------------------
// Kernel 3: FFN2 grouped GEMM (act @ w2[e]^T), scaled by combine weight.
// grid = (HD/128 = 8, NE*32), 256 threads, same pipeline, fp16 MMA.
// ---------------------------------------------------------------------------
__global__ __launch_bounds__(256, 2) void k_ffn2() {
    int e  = blockIdx.y >> 5;
    int mt = blockIdx.y & 31;
    int cnt = g_counts[e];
    int m0 = mt * 128;
    if (m0 >= cnt) return;
    int n0 = blockIdx.x * 128;

    extern __shared__ char dsm[];
    __shared__ int s_tok[128];

    int tid = threadIdx.x;
    if (tid < 128) {
        int idx = m0 + tid;
        s_tok[tid] = (idx < cnt) ? g_tok[e * TQ + idx] : -1;
    }
    __syncthreads();

    int warp = tid >> 5, lane = tid & 31;
    int wm = warp >> 1, wn = warp & 1;
    int g = lane >> 2, tg = lane & 3;

    int lrow = tid >> 1, lcb = (tid & 1) * 4;
    int atok = s_tok[lrow];
    uint32_t za = (atok >= 0) ? 16u : 0u;
    const __half* aptr = g_acth + (size_t)(atok >= 0 ? atok : 0) * FD + lcb * 8;
    const __half* bptr = g_w2h + ((size_t)e * HD + n0 + lrow) * FD + lcb * 8;

    uint32_t sbase = s2u(dsm);
    uint32_t offs[4];
#pragma unroll
    for (int c = 0; c < 4; c++)
        offs[c] = (uint32_t)(lrow * 128 + (((lcb + c) ^ (lrow & 7)) << 4));

    int j = lane >> 3, r = lane & 7;
    uint32_t aoffA = (uint32_t)((wm * 32 + ((j & 1) << 3) + r) * 128);
    uint32_t aoffB = (uint32_t)((wn * 64 + ((j >> 1) << 3) + r) * 128);
    int cjA = j >> 1, cjB = j & 1;
    uint32_t xa[4], xb[4];
#pragma unroll
    for (int ks = 0; ks < 4; ks++) {
        xa[ks] = (uint32_t)((((2 * ks + cjA) ^ r) << 4));
        xb[ks] = (uint32_t)((((2 * ks + cjB) ^ r) << 4));
    }

    float acc[2][8][4];
#pragma unroll
    for (int mi = 0; mi < 2; mi++)
#pragma unroll
        for (int ni = 0; ni < 8; ni++)
#pragma unroll
            for (int q = 0; q < 4; q++) acc[mi][ni][q] = 0.f;

    const int NKC = FD / 64;   // 32
    LOAD_STAGE(0, 0);
    LOAD_STAGE(64, 1);

    for (int i = 0; i < NKC; i++) {
        asm volatile("cp.async.wait_group 1;" ::: "memory");
        __syncthreads();
        if (i + 2 < NKC) {
            int st = (i + 2) % 3;
            LOAD_STAGE((i + 2) * 64, st);
        } else {
            asm volatile("cp.async.commit_group;" ::: "memory");
        }
        CHUNK_MMA(i % 3);
    }

#pragma unroll
    for (int mi = 0; mi < 2; mi++) {
        int rl0 = wm * 32 + mi * 16 + g;
        int t0 = s_tok[rl0], t1 = s_tok[rl0 + 8];
        float w0 = (t0 >= 0) ? g_wt[t0] : 0.f;
        float w1v = (t1 >= 0) ? g_wt[t1] : 0.f;
#pragma unroll
        for (int ni = 0; ni < 8; ni++) {
            int col = n0 + wn * 64 + ni * 8 + tg * 2;
            float* c = acc[mi][ni];
            if (t0 >= 0)
                *(float2*)(g_y + (size_t)t0 * HD + col) =
                    make_float2(w0 * c[0], w0 * c[1]);
            if (t1 >= 0)
                *(float2*)(g_y + (size_t)t1 * HD + col) =
                    make_float2(w1v * c[2], w1v * c[3]);
        }
    }
}

// ---------------------------------------------------------------------------
// Kernel 4: combine the two expert contributions per token (full overwrite).
// ---------------------------------------------------------------------------
__global__ __launch_bounds__(256) void k_combine(float* __restrict__ out) {
    int i = blockIdx.x * 256 + threadIdx.x;
    int t = i >> 8;
    int c = i & 255;
    float4 a = ((const float4*)(g_y + (size_t)(2 * t) * HD))[c];
    float4 b = ((const float4*)(g_y + (size_t)(2 * t + 1) * HD))[c];
    ((float4*)out)[i] = make_float4(a.x + b.x, a.y + b.y, a.z + b.z, a.w + b.w);
}

// ---------------------------------------------------------------------------
// Launch. Submission order keeps ffn1 at kernel index 3 for ncu:
// router=0, cvt_w1=1, cvt_w2=2 (side stream, overlaps ffn1), ffn1=3.
// ---------------------------------------------------------------------------
extern "C" void kernel_launch(void* const* d_in, const int* in_sizes, int n_in,
                              void* d_out, int out_size) {
    const float* hs = (const float*)d_in[0];
    const float* gw = (const float*)d_in[1];
    const float* w1 = (const float*)d_in[2];
    const float* w2 = (const float*)d_in[3];
    float* out = (float*)d_out;
    float* logits = (out_size >= TQ * HD + TQ * NE) ? out + (size_t)TQ * HD
                                                    : nullptr;

    static const int DSMEM = 98304;  // 3 stages x 32KB -> 2 CTAs/SM
    static cudaStream_t s2 = nullptr;
    static cudaEvent_t evFork, evJoin;
    if (!s2) {
        cudaFuncSetAttribute(k_ffn1, cudaFuncAttributeMaxDynamicSharedMemorySize, DSMEM);
        cudaFuncSetAttribute(k_ffn2, cudaFuncAttributeMaxDynamicSharedMemorySize, DSMEM);
        cudaStreamCreateWithFlags(&s2, cudaStreamNonBlocking);
        cudaEventCreateWithFlags(&evFork, cudaEventDisableTiming);
        cudaEventCreateWithFlags(&evJoin, cudaEventDisableTiming);
    }

    void* w1h; cudaGetSymbolAddress(&w1h, g_w1h);
    void* w2h; cudaGetSymbolAddress(&w2h, g_w2h);
    void* hsh; cudaGetSymbolAddress(&hsh, g_hsh);
    int*  cnts; cudaGetSymbolAddress((void**)&cnts, g_counts);

    cudaMemsetAsync(cnts, 0, NE * sizeof(int));                       // node, not kernel
    k_router<<<TQ / 8, 256>>>(hs, gw, logits, (__half*)hsh);          // kernel 0 (+hs cvt)
    k_cvt_h<<<(NE * 2 * FD * HD / 8) / 256, 256>>>((const float4*)w1, // kernel 1
                                                   (uint4*)w1h, NE * 2 * FD * HD / 8);
    // fork: cvt_w2 on side stream, overlaps ffn1
    cudaEventRecord(evFork, 0);
    cudaStreamWaitEvent(s2, evFork, 0);
    k_cvt_h<<<(NE * HD * FD / 8) / 256, 256, 0, s2>>>((const float4*)w2, // kernel 2
                                                      (uint4*)w2h, NE * HD * FD / 8);
    k_ffn1<<<dim3(FD / 64, NE * 32), 256, DSMEM>>>();                 // kernel 3 (profiled)
    // join: ffn2 needs w2h
    cudaEventRecord(evJoin, s2);
    cudaStreamWaitEvent(0, evJoin, 0);
    k_ffn2<<<dim3(HD / 128, NE * 32), 256, DSMEM>>>();                // kernel 4
    k_combine<<<(TQ * HD / 4) / 256, 256>>>(out);                     // kernel 5
}

// round 12
// speedup vs baseline: 1.5369x; 1.0902x over previous
#include <cuda_runtime.h>
#include <cuda_fp16.h>
#include <cstdint>

// Problem constants
#define TQ 4096   // tokens
#define HD 1024   // hidden
#define FD 2048   // ffn dim (w1 rows: [gate(0..FD), up(FD..2FD)])
#define NE 8      // experts
#define NK 2      // top-k

// ---------------------------------------------------------------------------
// Scratch (device globals; runtime allocation is forbidden)
// ---------------------------------------------------------------------------
__device__ int    g_counts[NE];
__device__ int    g_tok[NE * TQ];
__device__ float  g_wt[TQ * NK];
__device__ float  g_y[(size_t)TQ * NK * HD];
__device__ __half g_acth[(size_t)TQ * NK * FD];      // fp16 silu(g)*u
__device__ __half g_hsh[(size_t)TQ * HD];            // fp16 hs (written by router)
__device__ __half g_w1h[(size_t)NE * 2 * FD * HD];   // fp16 w1 (67MB)
__device__ __half g_w2h[(size_t)NE * HD * FD];       // fp16 w2 (34MB)

// ---------------------------------------------------------------------------
// Helpers
// ---------------------------------------------------------------------------
__device__ __forceinline__ uint32_t f2h2(float lo, float hi) {
    uint32_t r;   // f16x2: lo half <- 2nd operand
    asm("cvt.rn.f16x2.f32 %0, %1, %2;" : "=r"(r) : "f"(hi), "f"(lo));
    return r;
}
__device__ __forceinline__ uint32_t s2u(const void* p) {
    uint32_t a;
    asm("{ .reg .u64 t; cvta.to.shared.u64 t, %1; cvt.u32.u64 %0, t; }"
        : "=r"(a) : "l"(p));
    return a;
}
// fp16 m16n8k16, fp32 accumulate: 2048 MACs per instruction.
__device__ __forceinline__ void mma_f16(float* c, const uint32_t* a,
                                        uint32_t b0, uint32_t b1) {
    asm volatile(
        "mma.sync.aligned.m16n8k16.row.col.f32.f16.f16.f32 "
        "{%0,%1,%2,%3}, {%4,%5,%6,%7}, {%8,%9}, {%0,%1,%2,%3};"
        : "+f"(c[0]), "+f"(c[1]), "+f"(c[2]), "+f"(c[3])
        : "r"(a[0]), "r"(a[1]), "r"(a[2]), "r"(a[3]), "r"(b0), "r"(b1));
}
// ldmatrix x4 b16: 4x (8 rows x 16B). Delivers the canonical fp16 fragments.
__device__ __forceinline__ void ldsm4(uint32_t* r, uint32_t addr) {
    asm volatile("ldmatrix.sync.aligned.m8n8.x4.shared.b16 {%0,%1,%2,%3}, [%4];"
                 : "=r"(r[0]), "=r"(r[1]), "=r"(r[2]), "=r"(r[3]) : "r"(addr));
}
__device__ __forceinline__ float silu(float x) {
    return x / (1.0f + __expf(-x));
}

// 16B cp.async with zero-fill when sz==0 (invalid A rows)
#define CPA16(sa, ga, sz)                                                      \
    asm volatile("cp.async.cg.shared.global [%0], [%1], 16, %2;"               \
                 :: "r"(sa), "l"(ga), "r"(sz) : "memory")

// mbarrier ops (all compiled fine on sm_103 in earlier rounds)
#define MBAR_INIT(a, c)                                                        \
    asm volatile("mbarrier.init.shared.b64 [%0], %1;" :: "r"(a), "r"(c) : "memory")
#define MBAR_ARRIVE(a)                                                         \
    asm volatile("mbarrier.arrive.shared.b64 _, [%0];" :: "r"(a) : "memory")
// arrive on mbarrier when all of this thread's prior cp.asyncs complete
#define CPA_MBAR(a)                                                            \
    asm volatile("cp.async.mbarrier.arrive.noinc.shared.b64 [%0];"             \
                 :: "r"(a) : "memory")
#define MBAR_WAIT(mbar, ph) do {                                               \
    uint32_t _m = (mbar); uint32_t _p = (uint32_t)(ph); uint32_t _d;           \
    asm volatile("{\n\t.reg .pred p;\n\t"                                      \
        "mbarrier.try_wait.parity.acquire.cta.shared::cta.b64 p, [%1], %2;\n\t"\
        "selp.b32 %0, 1, 0, p;\n\t}" : "=r"(_d) : "r"(_m), "r"(_p) : "memory");\
    if (!_d) {                                                                 \
        asm volatile("{\n\t.reg .pred P1;\n\t"                                 \
            "WL_%=:\n\t"                                                       \
            "mbarrier.try_wait.parity.acquire.cta.shared::cta.b64 P1, [%0], %1, 0x989680;\n\t" \
            "@P1 bra.uni WD_%=;\n\t"                                           \
            "bra.uni WL_%=;\n\t"                                               \
            "WD_%=:\n\t}" :: "r"(_m), "r"(_p) : "memory");                     \
    }                                                                          \
} while (0)

// Stage: A 128 rows x 64 halves (16KB) + B 128 rows x 64 halves (16KB) = 32KB.
// Row = 128B = 8 x 16B chunks; swizzle: phys chunk = chunk ^ (row & 7).
// 256 threads: 2 threads per row, 4 chunks each for A and B.
#define LOAD_STAGE(KC, ST) do {                                                \
    uint32_t _b = sbase + (uint32_t)(ST) * 32768u;                             \
    const __half* _a = aptr + (KC);                                            \
    const __half* _w = bptr + (KC);                                            \
    _Pragma("unroll")                                                          \
    for (int _c = 0; _c < 4; _c++) {                                           \
        CPA16(_b + offs[_c], _a + _c * 8, za);                                 \
        CPA16(_b + 16384u + offs[_c], _w + _c * 8, 16u);                       \
    }                                                                          \
} while (0)

// One K=64 chunk: 4 k16 steps of (ldsm frags -> 16 MMAs), single frag buffer.
// After the LAST LDSM the thread arrives (release) on the stage's free
// mbarrier so producers may overwrite it while our final MMAs still run.
#define CHUNK_MMA_REL(STOFF, FMB) do {                                         \
    uint32_t _sA = sbase + (STOFF);                                            \
    uint32_t _sB = _sA + 16384u;                                               \
    _Pragma("unroll")                                                          \
    for (int ks = 0; ks < 4; ks++) {                                           \
        uint32_t br_[4][4];                                                    \
        _Pragma("unroll")                                                      \
        for (int nip = 0; nip < 4; nip++)                                      \
            ldsm4(br_[nip], _sB + aoffB + nip * 2048u + xb[ks]);               \
        uint32_t ar_[2][4];                                                    \
        _Pragma("unroll")                                                      \
        for (int mi = 0; mi < 2; mi++)                                         \
            ldsm4(ar_[mi], _sA + aoffA + mi * 2048u + xa[ks]);                 \
        if (ks == 3) MBAR_ARRIVE(FMB);                                         \
        _Pragma("unroll")                                                      \
        for (int mi = 0; mi < 2; mi++)                                         \
            _Pragma("unroll")                                                  \
            for (int ni = 0; ni < 8; ni++)                                     \
                mma_f16(acc[mi][ni], ar_[mi],                                  \
                        br_[ni >> 1][2 * (ni & 1)],                            \
                        br_[ni >> 1][2 * (ni & 1) + 1]);                       \
    }                                                                          \
} while (0)

// smem: 3 stages x 32KB, then mbarriers: full[0..2] at +98304, free[0..2] at +98328
#define MB_FULL_OFF 98304u
#define MB_FREE_OFF 98328u
#define DSMEM_BYTES 98368

// ---------------------------------------------------------------------------
// Kernel 0b: fp32 -> fp16 round a tensor into scratch (8 floats/thread)
// ---------------------------------------------------------------------------
__global__ __launch_bounds__(256) void k_cvt_h(const float4* __restrict__ src,
                                               uint4* __restrict__ dst, int n8) {
    int i = blockIdx.x * 256 + threadIdx.x;
    if (i >= n8) return;
    float4 v0 = src[2 * i], v1 = src[2 * i + 1];
    uint4 o;
    o.x = f2h2(v0.x, v0.y);
    o.y = f2h2(v0.z, v0.w);
    o.z = f2h2(v1.x, v1.y);
    o.w = f2h2(v1.z, v1.w);
    dst[i] = o;
}

// ---------------------------------------------------------------------------
// Kernel 1: router. One warp per token. Also emits fp16 hs (fused cvt).
// ---------------------------------------------------------------------------
__global__ __launch_bounds__(256) void k_router(const float* __restrict__ hs,
                                                const float* __restrict__ gw,
                                                float* __restrict__ logits_out,
                                                __half* __restrict__ hsh_out) {
    __shared__ float sg[NE * HD];
    int tid = threadIdx.x;
    for (int i = tid; i < NE * HD; i += 256) sg[i] = gw[i];
    __syncthreads();

    int warp = tid >> 5, lane = tid & 31;
    int t = blockIdx.x * 8 + warp;
    const float* x = hs + (size_t)t * HD;
    __half* xo = hsh_out + (size_t)t * HD;

    float acc[NE];
#pragma unroll
    for (int e = 0; e < NE; e++) acc[e] = 0.f;
    for (int j = lane; j < HD; j += 32) {
        float xv = x[j];
        xo[j] = __float2half_rn(xv);
#pragma unroll
        for (int e = 0; e < NE; e++) acc[e] += xv * sg[e * HD + j];
    }
#pragma unroll
    for (int e = 0; e < NE; e++) {
#pragma unroll
        for (int off = 16; off; off >>= 1)
            acc[e] += __shfl_xor_sync(0xffffffffu, acc[e], off);
    }

    if (lane == 0) {
        if (logits_out) {
#pragma unroll
            for (int e = 0; e < NE; e++) logits_out[(size_t)t * NE + e] = acc[e];
        }
        float m1 = acc[0]; int i0 = 0;
#pragma unroll
        for (int e = 1; e < NE; e++) if (acc[e] > m1) { m1 = acc[e]; i0 = e; }
        float m2 = -3.4e38f; int i1 = 0;
#pragma unroll
        for (int e = 0; e < NE; e++)
            if (e != i0 && acc[e] > m2) { m2 = acc[e]; i1 = e; }
        float e2v = __expf(m2 - m1);
        float inv = 1.0f / (1.0f + e2v);

        int p0 = atomicAdd(&g_counts[i0], 1);
        g_tok[i0 * TQ + p0] = t * 2;
        g_wt[t * 2] = inv;
        int p1 = atomicAdd(&g_counts[i1], 1);
        g_tok[i1 * TQ + p1] = t * 2 + 1;
        g_wt[t * 2 + 1] = e2v * inv;
    }
}

// ---------------------------------------------------------------------------
// Kernel 2: FFN1 grouped GEMM with fused SiLU*up, fp16 MMA.
// CTA tile 128x128 mma cols (gate/up interleaved), 4x2 warps, warp 32x64.
// Barrier-free drift pipeline: per-stage mbarriers (full/free) replace the
// per-chunk __syncthreads, so warps keep independent phases and LDSM/MMA of
// different warps overlap on the crossbar/tensor pipes.
// grid = (FD/64 = 32, NE*32), 256 threads, 2 CTAs/SM.
// ---------------------------------------------------------------------------
__global__ __launch_bounds__(256, 2) void k_ffn1() {
    int e  = blockIdx.y >> 5;
    int mt = blockIdx.y & 31;
    int cnt = g_counts[e];
    int m0 = mt * 128;
    if (m0 >= cnt) return;
    int n0 = blockIdx.x * 64;

    extern __shared__ char dsm[];
    __shared__ int s_tok[128];

    int tid = threadIdx.x;
    if (tid < 128) {
        int idx = m0 + tid;
        s_tok[tid] = (idx < cnt) ? g_tok[e * TQ + idx] : -1;
    }

    uint32_t sbase = s2u(dsm);
    uint32_t mbF = sbase + MB_FULL_OFF;
    uint32_t mbE = sbase + MB_FREE_OFF;
    if (tid == 0) {
#pragma unroll
        for (int s = 0; s < 3; s++) {
            MBAR_INIT(mbF + 8u * s, 256);
            MBAR_INIT(mbE + 8u * s, 256);
        }
    }
    __syncthreads();

    int warp = tid >> 5, lane = tid & 31;
    int wm = warp >> 1, wn = warp & 1;      // 4x2 warps, warp tile 32x64
    int g = lane >> 2, tg = lane & 3;

    // loader: 2 threads per tile row, 4 x 16B (8 halves) chunks each
    int lrow = tid >> 1, lcb = (tid & 1) * 4;
    int atok = s_tok[lrow];
    uint32_t za = (atok >= 0) ? 16u : 0u;
    const __half* aptr = g_hsh + (size_t)(atok >= 0 ? (atok >> 1) : 0) * HD + lcb * 8;
    int wrow = (lrow & 1) ? (FD + n0 + (lrow >> 1)) : (n0 + (lrow >> 1));
    const __half* bptr = g_w1h + ((size_t)e * 2 * FD + wrow) * HD + lcb * 8;

    uint32_t offs[4];
#pragma unroll
    for (int c = 0; c < 4; c++)
        offs[c] = (uint32_t)(lrow * 128 + (((lcb + c) ^ (lrow & 7)) << 4));

    // ldmatrix per-lane address components (row = 128B)
    int j = lane >> 3, r = lane & 7;
    uint32_t aoffA = (uint32_t)((wm * 32 + ((j & 1) << 3) + r) * 128);
    uint32_t aoffB = (uint32_t)((wn * 64 + ((j >> 1) << 3) + r) * 128);
    int cjA = j >> 1, cjB = j & 1;
    uint32_t xa[4], xb[4];
#pragma unroll
    for (int ks = 0; ks < 4; ks++) {
        xa[ks] = (uint32_t)((((2 * ks + cjA) ^ r) << 4));
        xb[ks] = (uint32_t)((((2 * ks + cjB) ^ r) << 4));
    }

    float acc[2][8][4];
#pragma unroll
    for (int mi = 0; mi < 2; mi++)
#pragma unroll
        for (int ni = 0; ni < 8; ni++)
#pragma unroll
            for (int q = 0; q < 4; q++) acc[mi][ni][q] = 0.f;

    const int NKC = HD / 64;   // 16
    // Prologue: load chunks 0,1 (stages fresh, no waits)
    LOAD_STAGE(0, 0);  CPA_MBAR(mbF + 0u);
    LOAD_STAGE(64, 1); CPA_MBAR(mbF + 8u);

    int sc = 0, cpar = 0;            // consumer stage + parity
    int sp = 2, ppar = 0, pwait = 0; // producer stage + parity
    for (int i = 0; i < NKC; i++) {
        // producer: load chunk i+2 into stage sp
        int jj = i + 2;
        if (jj < NKC) {
            if (pwait) MBAR_WAIT(mbE + 8u * sp, ppar);
            LOAD_STAGE(jj * 64, sp);
            CPA_MBAR(mbF + 8u * sp);
            sp++;
            if (sp == 3) { sp = 0; if (pwait) ppar ^= 1; pwait = 1; }
        }
        // consumer: chunk i from stage sc
        MBAR_WAIT(mbF + 8u * sc, cpar);
        CHUNK_MMA_REL((uint32_t)sc * 32768u, mbE + 8u * sc);
        sc++;
        if (sc == 3) { sc = 0; cpar ^= 1; }
    }

    // Epilogue: even mma col = gate, odd = up; write fp16 activation.
#pragma unroll
    for (int mi = 0; mi < 2; mi++) {
        int rl0 = wm * 32 + mi * 16 + g;
        int t0 = s_tok[rl0], t1 = s_tok[rl0 + 8];
#pragma unroll
        for (int ni = 0; ni < 8; ni++) {
            int colg = n0 + wn * 32 + ni * 4 + tg;
            float* c = acc[mi][ni];
            if (t0 >= 0)
                g_acth[(size_t)t0 * FD + colg] = __float2half_rn(silu(c[0]) * c[1]);
            if (t1 >= 0)
                g_acth[(size_t)t1 * FD + colg] = __float2half_rn(silu(c[2]) * c[3]);
        }
    }
}

// ---------------------------------------------------------------------------
// Kernel 3: FFN2 grouped GEMM (act @ w2[e]^T), scaled by combine weight.
// grid = (HD/128 = 8, NE*32), 256 threads, same drift pipeline.
// ---------------------------------------------------------------------------
__global__ __launch_bounds__(256, 2) void k_ffn2() {
    int e  = blockIdx.y >> 5;
    int mt = blockIdx.y & 31;
    int cnt = g_counts[e];
    int m0 = mt * 128;
    if (m0 >= cnt) return;
    int n0 = blockIdx.x * 128;

    extern __shared__ char dsm[];
    __shared__ int s_tok[128];

    int tid = threadIdx.x;
    if (tid < 128) {
        int idx = m0 + tid;
        s_tok[tid] = (idx < cnt) ? g_tok[e * TQ + idx] : -1;
    }

    uint32_t sbase = s2u(dsm);
    uint32_t mbF = sbase + MB_FULL_OFF;
    uint32_t mbE = sbase + MB_FREE_OFF;
    if (tid == 0) {
#pragma unroll
        for (int s = 0; s < 3; s++) {
            MBAR_INIT(mbF + 8u * s, 256);
            MBAR_INIT(mbE + 8u * s, 256);
        }
    }
    __syncthreads();

    int warp = tid >> 5, lane = tid & 31;
    int wm = warp >> 1, wn = warp & 1;
    int g = lane >> 2, tg = lane & 3;

    int lrow = tid >> 1, lcb = (tid & 1) * 4;
    int atok = s_tok[lrow];
    uint32_t za = (atok >= 0) ? 16u : 0u;
    const __half* aptr = g_acth + (size_t)(atok >= 0 ? atok : 0) * FD + lcb * 8;
    const __half* bptr = g_w2h + ((size_t)e * HD + n0 + lrow) * FD + lcb * 8;

    uint32_t offs[4];
#pragma unroll
    for (int c = 0; c < 4; c++)
        offs[c] = (uint32_t)(lrow * 128 + (((lcb + c) ^ (lrow & 7)) << 4));

    int j = lane >> 3, r = lane & 7;
    uint32_t aoffA = (uint32_t)((wm * 32 + ((j & 1) << 3) + r) * 128);
    uint32_t aoffB = (uint32_t)((wn * 64 + ((j >> 1) << 3) + r) * 128);
    int cjA = j >> 1, cjB = j & 1;
    uint32_t xa[4], xb[4];
#pragma unroll
    for (int ks = 0; ks < 4; ks++) {
        xa[ks] = (uint32_t)((((2 * ks + cjA) ^ r) << 4));
        xb[ks] = (uint32_t)((((2 * ks + cjB) ^ r) << 4));
    }

    float acc[2][8][4];
#pragma unroll
    for (int mi = 0; mi < 2; mi++)
#pragma unroll
        for (int ni = 0; ni < 8; ni++)
#pragma unroll
            for (int q = 0; q < 4; q++) acc[mi][ni][q] = 0.f;

    const int NKC = FD / 64;   // 32
    LOAD_STAGE(0, 0);  CPA_MBAR(mbF + 0u);
    LOAD_STAGE(64, 1); CPA_MBAR(mbF + 8u);

    int sc = 0, cpar = 0;
    int sp = 2, ppar = 0, pwait = 0;
    for (int i = 0; i < NKC; i++) {
        int jj = i + 2;
        if (jj < NKC) {
            if (pwait) MBAR_WAIT(mbE + 8u * sp, ppar);
            LOAD_STAGE(jj * 64, sp);
            CPA_MBAR(mbF + 8u * sp);
            sp++;
            if (sp == 3) { sp = 0; if (pwait) ppar ^= 1; pwait = 1; }
        }
        MBAR_WAIT(mbF + 8u * sc, cpar);
        CHUNK_MMA_REL((uint32_t)sc * 32768u, mbE + 8u * sc);
        sc++;
        if (sc == 3) { sc = 0; cpar ^= 1; }
    }

#pragma unroll
    for (int mi = 0; mi < 2; mi++) {
        int rl0 = wm * 32 + mi * 16 + g;
        int t0 = s_tok[rl0], t1 = s_tok[rl0 + 8];
        float w0 = (t0 >= 0) ? g_wt[t0] : 0.f;
        float w1v = (t1 >= 0) ? g_wt[t1] : 0.f;
#pragma unroll
        for (int ni = 0; ni < 8; ni++) {
            int col = n0 + wn * 64 + ni * 8 + tg * 2;
            float* c = acc[mi][ni];
            if (t0 >= 0)
                *(float2*)(g_y + (size_t)t0 * HD + col) =
                    make_float2(w0 * c[0], w0 * c[1]);
            if (t1 >= 0)
                *(float2*)(g_y + (size_t)t1 * HD + col) =
                    make_float2(w1v * c[2], w1v * c[3]);
        }
    }
}

// ---------------------------------------------------------------------------
// Kernel 4: combine the two expert contributions per token (full overwrite).
// ---------------------------------------------------------------------------
__global__ __launch_bounds__(256) void k_combine(float* __restrict__ out) {
    int i = blockIdx.x * 256 + threadIdx.x;
    int t = i >> 8;
    int c = i & 255;
    float4 a = ((const float4*)(g_y + (size_t)(2 * t) * HD))[c];
    float4 b = ((const float4*)(g_y + (size_t)(2 * t + 1) * HD))[c];
    ((float4*)out)[i] = make_float4(a.x + b.x, a.y + b.y, a.z + b.z, a.w + b.w);
}

// ---------------------------------------------------------------------------
// Launch. Submission order keeps ffn1 at kernel index 3 for ncu:
// router=0, cvt_w1=1, cvt_w2=2 (side stream, overlaps ffn1), ffn1=3.
// ---------------------------------------------------------------------------
extern "C" void kernel_launch(void* const* d_in, const int* in_sizes, int n_in,
                              void* d_out, int out_size) {
    const float* hs = (const float*)d_in[0];
    const float* gw = (const float*)d_in[1];
    const float* w1 = (const float*)d_in[2];
    const float* w2 = (const float*)d_in[3];
    float* out = (float*)d_out;
    float* logits = (out_size >= TQ * HD + TQ * NE) ? out + (size_t)TQ * HD
                                                    : nullptr;

    static cudaStream_t s2 = nullptr;
    static cudaEvent_t evFork, evJoin;
    if (!s2) {
        cudaFuncSetAttribute(k_ffn1, cudaFuncAttributeMaxDynamicSharedMemorySize, DSMEM_BYTES);
        cudaFuncSetAttribute(k_ffn2, cudaFuncAttributeMaxDynamicSharedMemorySize, DSMEM_BYTES);
        cudaStreamCreateWithFlags(&s2, cudaStreamNonBlocking);
        cudaEventCreateWithFlags(&evFork, cudaEventDisableTiming);
        cudaEventCreateWithFlags(&evJoin, cudaEventDisableTiming);
    }

    void* w1h; cudaGetSymbolAddress(&w1h, g_w1h);
    void* w2h; cudaGetSymbolAddress(&w2h, g_w2h);
    void* hsh; cudaGetSymbolAddress(&hsh, g_hsh);
    int*  cnts; cudaGetSymbolAddress((void**)&cnts, g_counts);

    cudaMemsetAsync(cnts, 0, NE * sizeof(int));                       // node, not kernel
    k_router<<<TQ / 8, 256>>>(hs, gw, logits, (__half*)hsh);          // kernel 0 (+hs cvt)
    k_cvt_h<<<(NE * 2 * FD * HD / 8) / 256, 256>>>((const float4*)w1, // kernel 1
                                                   (uint4*)w1h, NE * 2 * FD * HD / 8);
    // fork: cvt_w2 on side stream, overlaps ffn1
    cudaEventRecord(evFork, 0);
    cudaStreamWaitEvent(s2, evFork, 0);
    k_cvt_h<<<(NE * HD * FD / 8) / 256, 256, 0, s2>>>((const float4*)w2, // kernel 2
                                                      (uint4*)w2h, NE * HD * FD / 8);
    k_ffn1<<<dim3(FD / 64, NE * 32), 256, DSMEM_BYTES>>>();           // kernel 3 (profiled)
    // join: ffn2 needs w2h
    cudaEventRecord(evJoin, s2);
    cudaStreamWaitEvent(0, evJoin, 0);
    k_ffn2<<<dim3(HD / 128, NE * 32), 256, DSMEM_BYTES>>>();          // kernel 4
    k_combine<<<(TQ * HD / 4) / 256, 256>>>(out);                     // kernel 5
}

// round 13
// speedup vs baseline: 1.5549x; 1.0117x over previous
#include <cuda_runtime.h>
#include <cuda_fp16.h>
#include <cstdint>

// Problem constants
#define TQ 4096   // tokens
#define HD 1024   // hidden
#define FD 2048   // ffn dim (w1 rows: [gate(0..FD), up(FD..2FD)])
#define NE 8      // experts
#define NK 2      // top-k

// ---------------------------------------------------------------------------
// Scratch (device globals; runtime allocation is forbidden)
// ---------------------------------------------------------------------------
__device__ int    g_counts[NE];
__device__ int    g_tok[NE * TQ];
__device__ float  g_wt[TQ * NK];
__device__ __half g_acth[(size_t)TQ * NK * FD];      // fp16 silu(g)*u
__device__ __half g_hsh[(size_t)TQ * HD];            // fp16 hs (written by router)
__device__ __half g_w1h[(size_t)NE * 2 * FD * HD];   // fp16 w1 (67MB)
__device__ __half g_w2h[(size_t)NE * HD * FD];       // fp16 w2 (34MB)

// ---------------------------------------------------------------------------
// Helpers
// ---------------------------------------------------------------------------
__device__ __forceinline__ uint32_t f2h2(float lo, float hi) {
    uint32_t r;   // f16x2: lo half <- 2nd operand
    asm("cvt.rn.f16x2.f32 %0, %1, %2;" : "=r"(r) : "f"(hi), "f"(lo));
    return r;
}
__device__ __forceinline__ uint32_t s2u(const void* p) {
    uint32_t a;
    asm("{ .reg .u64 t; cvta.to.shared.u64 t, %1; cvt.u32.u64 %0, t; }"
        : "=r"(a) : "l"(p));
    return a;
}
// fp16 m16n8k16, fp32 accumulate: 2048 MACs per instruction.
__device__ __forceinline__ void mma_f16(float* c, const uint32_t* a,
                                        uint32_t b0, uint32_t b1) {
    asm volatile(
        "mma.sync.aligned.m16n8k16.row.col.f32.f16.f16.f32 "
        "{%0,%1,%2,%3}, {%4,%5,%6,%7}, {%8,%9}, {%0,%1,%2,%3};"
        : "+f"(c[0]), "+f"(c[1]), "+f"(c[2]), "+f"(c[3])
        : "r"(a[0]), "r"(a[1]), "r"(a[2]), "r"(a[3]), "r"(b0), "r"(b1));
}
// ldmatrix x4 b16: 4x (8 rows x 16B). Delivers the canonical fp16 fragments.
__device__ __forceinline__ void ldsm4(uint32_t* r, uint32_t addr) {
    asm volatile("ldmatrix.sync.aligned.m8n8.x4.shared.b16 {%0,%1,%2,%3}, [%4];"
                 : "=r"(r[0]), "=r"(r[1]), "=r"(r[2]), "=r"(r[3]) : "r"(addr));
}
__device__ __forceinline__ float silu(float x) {
    return x / (1.0f + __expf(-x));
}
// fire-and-forget global fp32 add (exactly 2 adds per element across the
// whole launch -> commutative -> bit-deterministic result)
__device__ __forceinline__ void redadd(float* p, float v) {
    asm volatile("red.global.add.f32 [%0], %1;" :: "l"(p), "f"(v) : "memory");
}

// 16B cp.async with zero-fill when sz==0 (invalid A rows)
#define CPA16(sa, ga, sz)                                                      \
    asm volatile("cp.async.cg.shared.global [%0], [%1], 16, %2;"               \
                 :: "r"(sa), "l"(ga), "r"(sz) : "memory")

// mbarrier ops
#define MBAR_INIT(a, c)                                                        \
    asm volatile("mbarrier.init.shared.b64 [%0], %1;" :: "r"(a), "r"(c) : "memory")
#define MBAR_ARRIVE(a)                                                         \
    asm volatile("mbarrier.arrive.shared.b64 _, [%0];" :: "r"(a) : "memory")
#define CPA_MBAR(a)                                                            \
    asm volatile("cp.async.mbarrier.arrive.noinc.shared.b64 [%0];"             \
                 :: "r"(a) : "memory")
#define MBAR_WAIT(mbar, ph) do {                                               \
    uint32_t _m = (mbar); uint32_t _p = (uint32_t)(ph); uint32_t _d;           \
    asm volatile("{\n\t.reg .pred p;\n\t"                                      \
        "mbarrier.try_wait.parity.acquire.cta.shared::cta.b64 p, [%1], %2;\n\t"\
        "selp.b32 %0, 1, 0, p;\n\t}" : "=r"(_d) : "r"(_m), "r"(_p) : "memory");\
    if (!_d) {                                                                 \
        asm volatile("{\n\t.reg .pred P1;\n\t"                                 \
            "WL_%=:\n\t"                                                       \
            "mbarrier.try_wait.parity.acquire.cta.shared::cta.b64 P1, [%0], %1, 0x989680;\n\t" \
            "@P1 bra.uni WD_%=;\n\t"                                           \
            "bra.uni WL_%=;\n\t"                                               \
            "WD_%=:\n\t}" :: "r"(_m), "r"(_p) : "memory");                     \
    }                                                                          \
} while (0)

// Stage: A 128 rows x 64 halves (16KB) + B 128 rows x 64 halves (16KB) = 32KB.
// Row = 128B = 8 x 16B chunks; swizzle: phys chunk = chunk ^ (row & 7).
#define LOAD_STAGE(KC, ST) do {                                                \
    uint32_t _b = sbase + (uint32_t)(ST) * 32768u;                             \
    const __half* _a = aptr + (KC);                                            \
    const __half* _w = bptr + (KC);                                            \
    _Pragma("unroll")                                                          \
    for (int _c = 0; _c < 4; _c++) {                                           \
        CPA16(_b + offs[_c], _a + _c * 8, za);                                 \
        CPA16(_b + 16384u + offs[_c], _w + _c * 8, 16u);                       \
    }                                                                          \
} while (0)

// One K=64 chunk: 4 k16 steps of (ldsm frags -> 16 MMAs), single frag buffer.
// After the LAST LDSM the thread arrives (release) on the stage's free
// mbarrier so producers may overwrite it while our final MMAs still run.
#define CHUNK_MMA_REL(STOFF, FMB) do {                                         \
    uint32_t _sA = sbase + (STOFF);                                            \
    uint32_t _sB = _sA + 16384u;                                               \
    _Pragma("unroll")                                                          \
    for (int ks = 0; ks < 4; ks++) {                                           \
        uint32_t br_[4][4];                                                    \
        _Pragma("unroll")                                                      \
        for (int nip = 0; nip < 4; nip++)                                      \
            ldsm4(br_[nip], _sB + aoffB + nip * 2048u + xb[ks]);               \
        uint32_t ar_[2][4];                                                    \
        _Pragma("unroll")                                                      \
        for (int mi = 0; mi < 2; mi++)                                         \
            ldsm4(ar_[mi], _sA + aoffA + mi * 2048u + xa[ks]);                 \
        if (ks == 3) MBAR_ARRIVE(FMB);                                         \
        _Pragma("unroll")                                                      \
        for (int mi = 0; mi < 2; mi++)                                         \
            _Pragma("unroll")                                                  \
            for (int ni = 0; ni < 8; ni++)                                     \
                mma_f16(acc[mi][ni], ar_[mi],                                  \
                        br_[ni >> 1][2 * (ni & 1)],                            \
                        br_[ni >> 1][2 * (ni & 1) + 1]);                       \
    }                                                                          \
} while (0)

// smem: 3 stages x 32KB, then mbarriers: full[0..2] at +98304, free[0..2] at +98328
#define MB_FULL_OFF 98304u
#define MB_FREE_OFF 98328u
#define DSMEM_BYTES 98368

// ---------------------------------------------------------------------------
// Kernel 0b: fp32 -> fp16 round a tensor into scratch (8 floats/thread)
// ---------------------------------------------------------------------------
__global__ __launch_bounds__(256) void k_cvt_h(const float4* __restrict__ src,
                                               uint4* __restrict__ dst, int n8) {
    int i = blockIdx.x * 256 + threadIdx.x;
    if (i >= n8) return;
    float4 v0 = src[2 * i], v1 = src[2 * i + 1];
    uint4 o;
    o.x = f2h2(v0.x, v0.y);
    o.y = f2h2(v0.z, v0.w);
    o.z = f2h2(v1.x, v1.y);
    o.w = f2h2(v1.z, v1.w);
    dst[i] = o;
}

// ---------------------------------------------------------------------------
// Kernel 1: router. One warp per token. Also emits fp16 hs (fused cvt).
// ---------------------------------------------------------------------------
__global__ __launch_bounds__(256) void k_router(const float* __restrict__ hs,
                                                const float* __restrict__ gw,
                                                float* __restrict__ logits_out,
                                                __half* __restrict__ hsh_out) {
    __shared__ float sg[NE * HD];
    int tid = threadIdx.x;
    for (int i = tid; i < NE * HD; i += 256) sg[i] = gw[i];
    __syncthreads();

    int warp = tid >> 5, lane = tid & 31;
    int t = blockIdx.x * 8 + warp;
    const float* x = hs + (size_t)t * HD;
    __half* xo = hsh_out + (size_t)t * HD;

    float acc[NE];
#pragma unroll
    for (int e = 0; e < NE; e++) acc[e] = 0.f;
    for (int j = lane; j < HD; j += 32) {
        float xv = x[j];
        xo[j] = __float2half_rn(xv);
#pragma unroll
        for (int e = 0; e < NE; e++) acc[e] += xv * sg[e * HD + j];
    }
#pragma unroll
    for (int e = 0; e < NE; e++) {
#pragma unroll
        for (int off = 16; off; off >>= 1)
            acc[e] += __shfl_xor_sync(0xffffffffu, acc[e], off);
    }

    if (lane == 0) {
        if (logits_out) {
#pragma unroll
            for (int e = 0; e < NE; e++) logits_out[(size_t)t * NE + e] = acc[e];
        }
        float m1 = acc[0]; int i0 = 0;
#pragma unroll
        for (int e = 1; e < NE; e++) if (acc[e] > m1) { m1 = acc[e]; i0 = e; }
        float m2 = -3.4e38f; int i1 = 0;
#pragma unroll
        for (int e = 0; e < NE; e++)
            if (e != i0 && acc[e] > m2) { m2 = acc[e]; i1 = e; }
        float e2v = __expf(m2 - m1);
        float inv = 1.0f / (1.0f + e2v);

        int p0 = atomicAdd(&g_counts[i0], 1);
        g_tok[i0 * TQ + p0] = t * 2;
        g_wt[t * 2] = inv;
        int p1 = atomicAdd(&g_counts[i1], 1);
        g_tok[i1 * TQ + p1] = t * 2 + 1;
        g_wt[t * 2 + 1] = e2v * inv;
    }
}

// ---------------------------------------------------------------------------
// Kernel 2: FFN1 grouped GEMM with fused SiLU*up, fp16 MMA.
// CTA tile 128x128 mma cols (gate/up interleaved), 4x2 warps, warp 32x64.
// Barrier-free drift pipeline (per-stage mbarriers; no __syncthreads in loop).
// grid = (FD/64 = 32, NE*32), 256 threads, 2 CTAs/SM.
// ---------------------------------------------------------------------------
__global__ __launch_bounds__(256, 2) void k_ffn1() {
    int e  = blockIdx.y >> 5;
    int mt = blockIdx.y & 31;
    int cnt = g_counts[e];
    int m0 = mt * 128;
    if (m0 >= cnt) return;
    int n0 = blockIdx.x * 64;

    extern __shared__ char dsm[];
    __shared__ int s_tok[128];

    int tid = threadIdx.x;
    if (tid < 128) {
        int idx = m0 + tid;
        s_tok[tid] = (idx < cnt) ? g_tok[e * TQ + idx] : -1;
    }

    uint32_t sbase = s2u(dsm);
    uint32_t mbF = sbase + MB_FULL_OFF;
    uint32_t mbE = sbase + MB_FREE_OFF;
    if (tid == 0) {
#pragma unroll
        for (int s = 0; s < 3; s++) {
            MBAR_INIT(mbF + 8u * s, 256);
            MBAR_INIT(mbE + 8u * s, 256);
        }
    }
    __syncthreads();

    int warp = tid >> 5, lane = tid & 31;
    int wm = warp >> 1, wn = warp & 1;      // 4x2 warps, warp tile 32x64
    int g = lane >> 2, tg = lane & 3;

    // loader: 2 threads per tile row, 4 x 16B (8 halves) chunks each
    int lrow = tid >> 1, lcb = (tid & 1) * 4;
    int atok = s_tok[lrow];
    uint32_t za = (atok >= 0) ? 16u : 0u;
    const __half* aptr = g_hsh + (size_t)(atok >= 0 ? (atok >> 1) : 0) * HD + lcb * 8;
    int wrow = (lrow & 1) ? (FD + n0 + (lrow >> 1)) : (n0 + (lrow >> 1));
    const __half* bptr = g_w1h + ((size_t)e * 2 * FD + wrow) * HD + lcb * 8;

    uint32_t offs[4];
#pragma unroll
    for (int c = 0; c < 4; c++)
        offs[c] = (uint32_t)(lrow * 128 + (((lcb + c) ^ (lrow & 7)) << 4));

    // ldmatrix per-lane address components (row = 128B)
    int j = lane >> 3, r = lane & 7;
    uint32_t aoffA = (uint32_t)((wm * 32 + ((j & 1) << 3) + r) * 128);
    uint32_t aoffB = (uint32_t)((wn * 64 + ((j >> 1) << 3) + r) * 128);
    int cjA = j >> 1, cjB = j & 1;
    uint32_t xa[4], xb[4];
#pragma unroll
    for (int ks = 0; ks < 4; ks++) {
        xa[ks] = (uint32_t)((((2 * ks + cjA) ^ r) << 4));
        xb[ks] = (uint32_t)((((2 * ks + cjB) ^ r) << 4));
    }

    float acc[2][8][4];
#pragma unroll
    for (int mi = 0; mi < 2; mi++)
#pragma unroll
        for (int ni = 0; ni < 8; ni++)
#pragma unroll
            for (int q = 0; q < 4; q++) acc[mi][ni][q] = 0.f;

    const int NKC = HD / 64;   // 16
    LOAD_STAGE(0, 0);  CPA_MBAR(mbF + 0u);
    LOAD_STAGE(64, 1); CPA_MBAR(mbF + 8u);

    int sc = 0, cpar = 0;            // consumer stage + parity
    int sp = 2, ppar = 0, pwait = 0; // producer stage + parity
    for (int i = 0; i < NKC; i++) {
        int jj = i + 2;
        if (jj < NKC) {
            if (pwait) MBAR_WAIT(mbE + 8u * sp, ppar);
            LOAD_STAGE(jj * 64, sp);
            CPA_MBAR(mbF + 8u * sp);
            sp++;
            if (sp == 3) { sp = 0; if (pwait) ppar ^= 1; pwait = 1; }
        }
        MBAR_WAIT(mbF + 8u * sc, cpar);
        CHUNK_MMA_REL((uint32_t)sc * 32768u, mbE + 8u * sc);
        sc++;
        if (sc == 3) { sc = 0; cpar ^= 1; }
    }

    // Epilogue: even mma col = gate, odd = up; write fp16 activation.
#pragma unroll
    for (int mi = 0; mi < 2; mi++) {
        int rl0 = wm * 32 + mi * 16 + g;
        int t0 = s_tok[rl0], t1 = s_tok[rl0 + 8];
#pragma unroll
        for (int ni = 0; ni < 8; ni++) {
            int colg = n0 + wn * 32 + ni * 4 + tg;
            float* c = acc[mi][ni];
            if (t0 >= 0)
                g_acth[(size_t)t0 * FD + colg] = __float2half_rn(silu(c[0]) * c[1]);
            if (t1 >= 0)
                g_acth[(size_t)t1 * FD + colg] = __float2half_rn(silu(c[2]) * c[3]);
        }
    }
}

// ---------------------------------------------------------------------------
// Kernel 3: FFN2 grouped GEMM (act @ w2[e]^T), scaled by combine weight.
// Epilogue reduces DIRECTLY into d_out via red.global.add.f32 (out pre-zeroed;
// exactly two adds per element -> commutative -> deterministic).
// grid = (HD/128 = 8, NE*32), 256 threads, same drift pipeline.
// ---------------------------------------------------------------------------
__global__ __launch_bounds__(256, 2) void k_ffn2(float* __restrict__ out) {
    int e  = blockIdx.y >> 5;
    int mt = blockIdx.y & 31;
    int cnt = g_counts[e];
    int m0 = mt * 128;
    if (m0 >= cnt) return;
    int n0 = blockIdx.x * 128;

    extern __shared__ char dsm[];
    __shared__ int s_tok[128];

    int tid = threadIdx.x;
    if (tid < 128) {
        int idx = m0 + tid;
        s_tok[tid] = (idx < cnt) ? g_tok[e * TQ + idx] : -1;
    }

    uint32_t sbase = s2u(dsm);
    uint32_t mbF = sbase + MB_FULL_OFF;
    uint32_t mbE = sbase + MB_FREE_OFF;
    if (tid == 0) {
#pragma unroll
        for (int s = 0; s < 3; s++) {
            MBAR_INIT(mbF + 8u * s, 256);
            MBAR_INIT(mbE + 8u * s, 256);
        }
    }
    __syncthreads();

    int warp = tid >> 5, lane = tid & 31;
    int wm = warp >> 1, wn = warp & 1;
    int g = lane >> 2, tg = lane & 3;

    int lrow = tid >> 1, lcb = (tid & 1) * 4;
    int atok = s_tok[lrow];
    uint32_t za = (atok >= 0) ? 16u : 0u;
    const __half* aptr = g_acth + (size_t)(atok >= 0 ? atok : 0) * FD + lcb * 8;
    const __half* bptr = g_w2h + ((size_t)e * HD + n0 + lrow) * FD + lcb * 8;

    uint32_t offs[4];
#pragma unroll
    for (int c = 0; c < 4; c++)
        offs[c] = (uint32_t)(lrow * 128 + (((lcb + c) ^ (lrow & 7)) << 4));

    int j = lane >> 3, r = lane & 7;
    uint32_t aoffA = (uint32_t)((wm * 32 + ((j & 1) << 3) + r) * 128);
    uint32_t aoffB = (uint32_t)((wn * 64 + ((j >> 1) << 3) + r) * 128);
    int cjA = j >> 1, cjB = j & 1;
    uint32_t xa[4], xb[4];
#pragma unroll
    for (int ks = 0; ks < 4; ks++) {
        xa[ks] = (uint32_t)((((2 * ks + cjA) ^ r) << 4));
        xb[ks] = (uint32_t)((((2 * ks + cjB) ^ r) << 4));
    }

    float acc[2][8][4];
#pragma unroll
    for (int mi = 0; mi < 2; mi++)
#pragma unroll
        for (int ni = 0; ni < 8; ni++)
#pragma unroll
            for (int q = 0; q < 4; q++) acc[mi][ni][q] = 0.f;

    const int NKC = FD / 64;   // 32
    LOAD_STAGE(0, 0);  CPA_MBAR(mbF + 0u);
    LOAD_STAGE(64, 1); CPA_MBAR(mbF + 8u);

    int sc = 0, cpar = 0;
    int sp = 2, ppar = 0, pwait = 0;
    for (int i = 0; i < NKC; i++) {
        int jj = i + 2;
        if (jj < NKC) {
            if (pwait) MBAR_WAIT(mbE + 8u * sp, ppar);
            LOAD_STAGE(jj * 64, sp);
            CPA_MBAR(mbF + 8u * sp);
            sp++;
            if (sp == 3) { sp = 0; if (pwait) ppar ^= 1; pwait = 1; }
        }
        MBAR_WAIT(mbF + 8u * sc, cpar);
        CHUNK_MMA_REL((uint32_t)sc * 32768u, mbE + 8u * sc);
        sc++;
        if (sc == 3) { sc = 0; cpar ^= 1; }
    }

#pragma unroll
    for (int mi = 0; mi < 2; mi++) {
        int rl0 = wm * 32 + mi * 16 + g;
        int t0 = s_tok[rl0], t1 = s_tok[rl0 + 8];
        float w0 = (t0 >= 0) ? g_wt[t0] : 0.f;
        float w1v = (t1 >= 0) ? g_wt[t1] : 0.f;
#pragma unroll
        for (int ni = 0; ni < 8; ni++) {
            int col = n0 + wn * 64 + ni * 8 + tg * 2;
            float* c = acc[mi][ni];
            if (t0 >= 0) {
                float* p = out + (size_t)(t0 >> 1) * HD + col;
                redadd(p,     w0 * c[0]);
                redadd(p + 1, w0 * c[1]);
            }
            if (t1 >= 0) {
                float* p = out + (size_t)(t1 >> 1) * HD + col;
                redadd(p,     w1v * c[2]);
                redadd(p + 1, w1v * c[3]);
            }
        }
    }
}

// ---------------------------------------------------------------------------
// Launch. Side stream s2 runs cvt_w1 (overlaps router) then cvt_w2 (overlaps
// ffn1). Submission order keeps ffn1 at ncu kernel index 3:
// router=0, cvt_w1=1, cvt_w2=2, ffn1=3, ffn2=4.
// ---------------------------------------------------------------------------
extern "C" void kernel_launch(void* const* d_in, const int* in_sizes, int n_in,
                              void* d_out, int out_size) {
    const float* hs = (const float*)d_in[0];
    const float* gw = (const float*)d_in[1];
    const float* w1 = (const float*)d_in[2];
    const float* w2 = (const float*)d_in[3];
    float* out = (float*)d_out;
    float* logits = (out_size >= TQ * HD + TQ * NE) ? out + (size_t)TQ * HD
                                                    : nullptr;

    static cudaStream_t s2 = nullptr;
    static cudaEvent_t evFork, evJ1, evJ2;
    if (!s2) {
        cudaFuncSetAttribute(k_ffn1, cudaFuncAttributeMaxDynamicSharedMemorySize, DSMEM_BYTES);
        cudaFuncSetAttribute(k_ffn2, cudaFuncAttributeMaxDynamicSharedMemorySize, DSMEM_BYTES);
        cudaStreamCreateWithFlags(&s2, cudaStreamNonBlocking);
        cudaEventCreateWithFlags(&evFork, cudaEventDisableTiming);
        cudaEventCreateWithFlags(&evJ1, cudaEventDisableTiming);
        cudaEventCreateWithFlags(&evJ2, cudaEventDisableTiming);
    }

    void* w1h; cudaGetSymbolAddress(&w1h, g_w1h);
    void* w2h; cudaGetSymbolAddress(&w2h, g_w2h);
    void* hsh; cudaGetSymbolAddress(&hsh, g_hsh);
    int*  cnts; cudaGetSymbolAddress((void**)&cnts, g_counts);

    cudaMemsetAsync(cnts, 0, NE * sizeof(int));                       // node
    cudaMemsetAsync(out, 0, (size_t)TQ * HD * sizeof(float));         // node
    // fork side stream before router so cvt_w1 overlaps it
    cudaEventRecord(evFork, 0);
    cudaStreamWaitEvent(s2, evFork, 0);

    k_router<<<TQ / 8, 256>>>(hs, gw, logits, (__half*)hsh);          // kernel 0
    k_cvt_h<<<(NE * 2 * FD * HD / 8) / 256, 256, 0, s2>>>(            // kernel 1 (s2)
        (const float4*)w1, (uint4*)w1h, NE * 2 * FD * HD / 8);
    cudaEventRecord(evJ1, s2);
    k_cvt_h<<<(NE * HD * FD / 8) / 256, 256, 0, s2>>>(                // kernel 2 (s2)
        (const float4*)w2, (uint4*)w2h, NE * HD * FD / 8);
    cudaEventRecord(evJ2, s2);

    cudaStreamWaitEvent(0, evJ1, 0);                                  // ffn1 needs w1h
    k_ffn1<<<dim3(FD / 64, NE * 32), 256, DSMEM_BYTES>>>();           // kernel 3 (profiled)
    cudaStreamWaitEvent(0, evJ2, 0);                                  // ffn2 needs w2h
    k_ffn2<<<dim3(HD / 128, NE * 32), 256, DSMEM_BYTES>>>(out);       // kernel 4
}